// round 17
// baseline (speedup 1.0000x reference)
#include <cuda_runtime.h>
#include <cuda_bf16.h>
#include <cstdint>

#define B_SZ   2048
#define N_INST 8
#define N_FEAT 100
#define N_HID  40
#define NM     41
#define NC     40
#define NTHR   512

#define IMGA_C 17920
#define IMGB_C 19968
#define SLOTSZ 59904               // 3 * IMGB_C (holds 3 of either image)
#define NSLOT  14                  // ceil(40/3)

// ---- smem map (bytes) ----
#define SM_RL    0                 // rowlists u8 [40][144] = 5760
#define SM_TL    5760              // tile list u16[512] = 1024
#define SM_CNT   6784              // int CNT[40] + SOF[15] = 220 -> 256
#define SM_BIAS  7040              // 400 -> pad
#define SM_MB    7440              // 2 mbarriers
#define SM_RING  7488              // 2 x 59904 = 119808 -> 127296
#define SM_XS    127296            // X bf16 [129][112] hi+lo = 57792 -> 185088 (phase A)
#define XS_LO    28896
#define SM_HS    127296            // h bf16 [129][48] hi+lo = 24768 (overlays XS, phase B)
#define HS_LO    12384
#define SM_HA    185088            // h accum f32 [129][40] = 20640 -> 205728
#define SM_OS    152064            // out accum f32 [129][104] = 53664 -> 205728 (overlays XS tail + hA)
#define SM_TOTAL 205824

__device__ __align__(16) unsigned char g_imgA[N_INST * NC * IMGA_C];
__device__ __align__(16) unsigned char g_imgB[N_INST * NC * IMGB_C];

// ===================== helpers =====================
__device__ __forceinline__ uint32_t smem_u32(const void* p) {
    return (uint32_t)__cvta_generic_to_shared(p);
}
__device__ __forceinline__ void mbar_init(uint32_t mb, uint32_t n) {
    asm volatile("mbarrier.init.shared.b64 [%0], %1;" :: "r"(mb), "r"(n) : "memory");
}
__device__ __forceinline__ void mbar_expect(uint32_t mb, uint32_t bytes) {
    asm volatile("mbarrier.arrive.expect_tx.shared.b64 _, [%0], %1;" :: "r"(mb), "r"(bytes) : "memory");
}
__device__ __forceinline__ void mbar_wait(uint32_t mb, uint32_t ph) {
    asm volatile("{\n\t.reg .pred P;\nW_%=:\n\t"
                 "mbarrier.try_wait.parity.acquire.cta.shared::cta.b64 P, [%0], %1, 0x989680;\n\t"
                 "@P bra D_%=;\n\tbra W_%=;\nD_%=:\n\t}" :: "r"(mb), "r"(ph) : "memory");
}
__device__ __forceinline__ void bulk_cp(uint32_t dst, const void* src, uint32_t bytes, uint32_t mb) {
    asm volatile("cp.async.bulk.shared::cluster.global.mbarrier::complete_tx::bytes [%0], [%1], %2, [%3];"
                 :: "r"(dst), "l"(src), "r"(bytes), "r"(mb) : "memory");
}
__device__ __forceinline__ void mma_bf16(float* d, const uint32_t* a, uint32_t b0, uint32_t b1) {
    asm volatile("mma.sync.aligned.m16n8k16.row.col.f32.bf16.bf16.f32 "
                 "{%0,%1,%2,%3},{%4,%5,%6,%7},{%8,%9},{%0,%1,%2,%3};"
                 : "+f"(d[0]), "+f"(d[1]), "+f"(d[2]), "+f"(d[3])
                 : "r"(a[0]), "r"(a[1]), "r"(a[2]), "r"(a[3]), "r"(b0), "r"(b1));
}
__device__ __forceinline__ void mma_bf16_k8(float* d, uint32_t a0, uint32_t a1, uint32_t b0) {
    asm volatile("mma.sync.aligned.m16n8k8.row.col.f32.bf16.bf16.f32 "
                 "{%0,%1,%2,%3},{%4,%5},{%6},{%0,%1,%2,%3};"
                 : "+f"(d[0]), "+f"(d[1]), "+f"(d[2]), "+f"(d[3])
                 : "r"(a0), "r"(a1), "r"(b0));
}
__device__ __forceinline__ void ldm_x4(uint32_t* r, uint32_t a) {
    asm volatile("ldmatrix.sync.aligned.m8n8.x4.shared.b16 {%0,%1,%2,%3}, [%4];"
                 : "=r"(r[0]), "=r"(r[1]), "=r"(r[2]), "=r"(r[3]) : "r"(a));
}
__device__ __forceinline__ void ldm_x2(uint32_t* r, uint32_t a) {
    asm volatile("ldmatrix.sync.aligned.m8n8.x2.shared.b16 {%0,%1}, [%2];"
                 : "=r"(r[0]), "=r"(r[1]) : "r"(a));
}
__device__ __forceinline__ uint32_t pack_bf2(float a, float b) {
    __nv_bfloat162 t = __floats2bfloat162_rn(a, b);
    return *reinterpret_cast<uint32_t*>(&t);
}
__device__ __forceinline__ void split_pair(float a, float b, uint32_t& hi, uint32_t& lo) {
    const __nv_bfloat16 ah = __float2bfloat16(a), bh = __float2bfloat16(b);
    hi = pack_bf2(a, b);
    lo = pack_bf2(a - __bfloat162float(ah), b - __bfloat162float(bh));
}
__device__ __forceinline__ uint4 frag_word(float v00, float v01, float v10, float v11) {
    uint4 w; uint32_t h0, l0, h1, l1;
    split_pair(v00, v01, h0, l0);
    split_pair(v10, v11, h1, l1);
    w.x = h0; w.y = h1; w.z = l0; w.w = l1;
    return w;
}

// ===================== Kernel 1: G -> fragment images =====================
__global__ __launch_bounds__(256)
void compute_G_kernel(const float* __restrict__ A, const float* __restrict__ Bp) {
    __shared__ float AsT[NM * N_FEAT];
    __shared__ float Bs[NM * N_HID];
    __shared__ float sS[N_FEAT * N_HID];
    const int ic = blockIdx.x;
    const float* Ap  = A  + (size_t)ic * N_FEAT * NM;
    const float* Bpp = Bp + (size_t)ic * NM * N_HID;
    uint4* iA = reinterpret_cast<uint4*>(g_imgA + (size_t)ic * IMGA_C);
    uint4* iB = reinterpret_cast<uint4*>(g_imgB + (size_t)ic * IMGB_C);

    for (int idx = threadIdx.x; idx < N_FEAT * NM; idx += blockDim.x) {
        const int f = idx / NM, m = idx % NM;
        AsT[m * N_FEAT + f] = Ap[idx];
    }
    for (int idx = threadIdx.x; idx < NM * N_HID; idx += blockDim.x) Bs[idx] = Bpp[idx];
    __syncthreads();
    for (int t = threadIdx.x; t < 1000; t += blockDim.x) {
        const int fp = t / 20, hp = t % 20;
        float a00 = 0.f, a01 = 0.f, a10 = 0.f, a11 = 0.f;
#pragma unroll
        for (int m = 0; m < NM; m++) {
            const float2 a = *reinterpret_cast<const float2*>(&AsT[m * N_FEAT + fp * 2]);
            const float2 b = *reinterpret_cast<const float2*>(&Bs[m * N_HID + hp * 2]);
            a00 = fmaf(a.x, b.x, a00); a01 = fmaf(a.x, b.y, a01);
            a10 = fmaf(a.y, b.x, a10); a11 = fmaf(a.y, b.y, a11);
        }
        *reinterpret_cast<float2*>(&sS[(fp * 2)     * N_HID + hp * 2]) = make_float2(a00, a01);
        *reinterpret_cast<float2*>(&sS[(fp * 2 + 1) * N_HID + hp * 2]) = make_float2(a10, a11);
    }
    __syncthreads();
    for (int widx = threadIdx.x; widx < 7 * 5 * 32; widx += blockDim.x) {
        const int kst = widx / 160, rem = widx % 160;
        const int nt = rem / 32, T = rem % 32;
        const int q = T & 3, tr = T >> 2;
        const int n = nt * 8 + tr;
        float v[2][2];
#pragma unroll
        for (int half = 0; half < 2; half++)
#pragma unroll
            for (int lo = 0; lo < 2; lo++) {
                const int f = kst * 16 + q * 2 + half * 8 + lo;
                v[half][lo] = (f < N_FEAT) ? sS[f * N_HID + n] : 0.f;
            }
        iA[widx] = frag_word(v[0][0], v[0][1], v[1][0], v[1][1]);
    }
    for (int widx = threadIdx.x; widx < 3 * 13 * 32; widx += blockDim.x) {
        const int kst = widx / 416, rem = widx % 416;
        const int nt = rem / 32, T = rem % 32;
        const int q = T & 3, tr = T >> 2;
        const int f = nt * 8 + tr;
        float v[2][2];
#pragma unroll
        for (int half = 0; half < 2; half++)
#pragma unroll
            for (int lo = 0; lo < 2; lo++) {
                const int h = kst * 16 + q * 2 + half * 8 + lo;
                v[half][lo] = (f < N_FEAT && h < N_HID) ? sS[f * N_HID + h] : 0.f;
            }
        iB[widx] = frag_word(v[0][0], v[0][1], v[1][0], v[1][1]);
    }
}

// ===================== Kernel 2: staged sparse, 3-c slots, nt-half units =====================
__global__ __launch_bounds__(NTHR)
void tmsspd_main_kernel(const float* __restrict__ x, const float* __restrict__ mask,
                        const float* __restrict__ bfin, float* __restrict__ out) {
    extern __shared__ char smem[];
    const uint32_t sb = smem_u32(smem);
    unsigned char* RL = reinterpret_cast<unsigned char*>(smem + SM_RL);
    uint16_t* TL = reinterpret_cast<uint16_t*>(smem + SM_TL);
    int*   CNT   = reinterpret_cast<int*>(smem + SM_CNT);
    int*   SOF   = CNT + 40;
    float* biasS = reinterpret_cast<float*>(smem + SM_BIAS);
    float* hA = reinterpret_cast<float*>(smem + SM_HA);
    float* oS = reinterpret_cast<float*>(smem + SM_OS);

    const int i   = blockIdx.y;
    const int b0  = blockIdx.x * 128;
    const int tid = threadIdx.x;
    const int w   = tid >> 5;
    const int T   = tid & 31;
    const int q   = T & 3;
    const int jj  = ((T >> 3) & 1) * 8 + (T & 7);
    const int kh  = (T >> 4) * 16;
    const uint32_t mb0 = sb + SM_MB, mb1 = mb0 + 8;
    uint32_t par0 = 0, par1 = 0;
    const bool lead = (tid == 0);

    const unsigned char* imgA = g_imgA + (size_t)(i * NC) * IMGA_C;
    const unsigned char* imgB = g_imgB + (size_t)(i * NC) * IMGB_C;

    if (lead) { mbar_init(mb0, 1); mbar_init(mb1, 1); }

    // ---- row lists ----
    for (int c = w; c < NC; c += 16) {
        int base = 0;
#pragma unroll
        for (int ch = 0; ch < 4; ch++) {
            const int r = ch * 32 + T;
            const float m = mask[((size_t)(b0 + r) * N_INST + i) * NC + c];
            const unsigned bal = __ballot_sync(0xffffffffu, m != 0.f);
            const int pos = __popc(bal & ((1u << T) - 1u));
            if (m != 0.f) RL[c * 144 + base + pos] = (unsigned char)r;
            base += __popc(bal);
        }
        const int nt = (base + 15) >> 4;
        for (int j = base + T; j < nt * 16; j += 32) RL[c * 144 + j] = 128;
        if (T == 0) CNT[c] = nt;
    }
    // ---- XS ----
    for (int idx = tid; idx < 129 * 56; idx += NTHR) {
        const int r = idx / 56, kp = idx % 56;
        float2 v = make_float2(0.f, 0.f);
        if (r < 128 && kp < 50)
            v = *reinterpret_cast<const float2*>(&x[((size_t)(b0 + r) * N_INST + i) * N_FEAT + kp * 2]);
        uint32_t hi, lo; split_pair(v.x, v.y, hi, lo);
        *reinterpret_cast<uint32_t*>(smem + SM_XS + r * 224 + kp * 4) = hi;
        *reinterpret_cast<uint32_t*>(smem + SM_XS + XS_LO + r * 224 + kp * 4) = lo;
    }
    for (int idx = tid; idx < 5160; idx += NTHR) hA[idx] = 0.f;
    if (tid < N_FEAT) biasS[tid] = bfin[i * N_FEAT + tid];
    __syncthreads();
    if (tid == 0) {
        int n = 0;
        for (int c = 0; c < NC; c++) {
            if (c % 3 == 0) SOF[c / 3] = n;
            for (int tt = 0; tt < CNT[c]; tt++) TL[n++] = (uint16_t)(c | (tt << 8));
        }
        SOF[NSLOT] = n;
    }
    __syncthreads();

    // prologue: stage A slots 0,1
    if (lead) {
        mbar_expect(mb0, 3 * IMGA_C); bulk_cp(sb + SM_RING,          imgA,              3 * IMGA_C, mb0);
        mbar_expect(mb1, 3 * IMGA_C); bulk_cp(sb + SM_RING + SLOTSZ, imgA + 3 * IMGA_C, 3 * IMGA_C, mb1);
    }

    // ================= Phase A =================
    for (int s = 0; s < NSLOT; s++) {
        if (s & 1) { mbar_wait(mb1, par1); par1 ^= 1; }
        else       { mbar_wait(mb0, par0); par0 ^= 1; }
        const char* slotp = smem + SM_RING + (s & 1) * SLOTSZ;
        const int u0 = SOF[s], nu = (SOF[s + 1] - u0) * 2;

        for (int u = w; u < nu; u += 16) {
            const int e = TL[u0 + (u >> 1)];
            const int half = u & 1;
            const int c = e & 255, tt = e >> 8;
            const char* buf = slotp + (c - 3 * s) * IMGA_C;
            const unsigned char* rl = RL + c * 144 + tt * 16;
            const int myrow = rl[jj];
            const uint32_t ab = sb + SM_XS + myrow * 224 + kh;
            const int n0 = half ? 3 : 0;
            const int NN = half ? 2 : 3;
            float d[3][4];
#pragma unroll
            for (int j = 0; j < 3; j++)
#pragma unroll
                for (int k = 0; k < 4; k++) d[j][k] = 0.f;

#pragma unroll
            for (int kst = 0; kst < 6; kst++) {
                uint4 wv[3];
                for (int j = 0; j < NN; j++)
                    wv[j] = *reinterpret_cast<const uint4*>(buf + (((kst * 5 + n0 + j) * 32 + T) << 4));
                uint32_t ah[4], al[4];
                ldm_x4(ah, ab + kst * 32);
                ldm_x4(al, ab + XS_LO + kst * 32);
                for (int j = 0; j < NN; j++) mma_bf16(d[j], ah, wv[j].x, wv[j].y);
                for (int j = 0; j < NN; j++) mma_bf16(d[j], ah, wv[j].z, wv[j].w);
                for (int j = 0; j < NN; j++) mma_bf16(d[j], al, wv[j].x, wv[j].y);
            }
            {   // k8 tail (f 96..103)
                uint32_t ah[2], al[2];
                ldm_x2(ah, sb + SM_XS + myrow * 224 + 192);
                ldm_x2(al, sb + SM_XS + XS_LO + myrow * 224 + 192);
                for (int j = 0; j < NN; j++) {
                    const uint4 wv = *reinterpret_cast<const uint4*>(buf + (((30 + n0 + j) * 32 + T) << 4));
                    mma_bf16_k8(d[j], ah[0], ah[1], wv.x);
                    mma_bf16_k8(d[j], ah[0], ah[1], wv.z);
                    mma_bf16_k8(d[j], al[0], al[1], wv.x);
                }
            }
            const int ra = rl[T >> 2], rb = rl[(T >> 2) + 8];
            for (int j = 0; j < NN; j++) {
                const int col = (n0 + j) * 8 + q * 2;
                atomicAdd(&hA[ra * 40 + col],     d[j][0]);
                atomicAdd(&hA[ra * 40 + col + 1], d[j][1]);
                atomicAdd(&hA[rb * 40 + col],     d[j][2]);
                atomicAdd(&hA[rb * 40 + col + 1], d[j][3]);
            }
        }
        __syncthreads();
        if (lead && s + 2 < NSLOT) {
            const int ncs = (40 - 3 * (s + 2) < 3) ? (40 - 3 * (s + 2)) : 3;
            const uint32_t mb = (s & 1) ? mb1 : mb0;
            mbar_expect(mb, (uint32_t)(ncs * IMGA_C));
            bulk_cp(sb + SM_RING + (s & 1) * SLOTSZ, imgA + (size_t)(3 * (s + 2)) * IMGA_C,
                    (uint32_t)(ncs * IMGA_C), mb);
        }
    }

    // ---- stage B slots 0,1 ; HS from hA ; zero OS ----
    if (lead) {
        mbar_expect(mb0, 3 * IMGB_C); bulk_cp(sb + SM_RING,          imgB,              3 * IMGB_C, mb0);
        mbar_expect(mb1, 3 * IMGB_C); bulk_cp(sb + SM_RING + SLOTSZ, imgB + 3 * IMGB_C, 3 * IMGB_C, mb1);
    }
    for (int idx = tid; idx < 129 * 24; idx += NTHR) {
        const int r = idx / 24, kp = idx % 24;
        float2 v = make_float2(0.f, 0.f);
        if (r < 128 && kp < 20)
            v = *reinterpret_cast<const float2*>(&hA[r * 40 + kp * 2]);
        uint32_t hi, lo; split_pair(v.x, v.y, hi, lo);
        *reinterpret_cast<uint32_t*>(smem + SM_HS + r * 96 + kp * 4) = hi;
        *reinterpret_cast<uint32_t*>(smem + SM_HS + HS_LO + r * 96 + kp * 4) = lo;
    }
    __syncthreads();
    for (int idx = tid; idx < 13416; idx += NTHR) oS[idx] = 0.f;
    __syncthreads();

    // ================= Phase B =================
    for (int s = 0; s < NSLOT; s++) {
        if (s & 1) { mbar_wait(mb1, par1); par1 ^= 1; }
        else       { mbar_wait(mb0, par0); par0 ^= 1; }
        const char* slotp = smem + SM_RING + (s & 1) * SLOTSZ;
        const int u0 = SOF[s], nu = (SOF[s + 1] - u0) * 2;

        for (int u = w; u < nu; u += 16) {
            const int e = TL[u0 + (u >> 1)];
            const int half = u & 1;
            const int c = e & 255, tt = e >> 8;
            const char* buf = slotp + (c - 3 * s) * IMGB_C;
            const unsigned char* rl = RL + c * 144 + tt * 16;
            const int myrow = rl[jj];
            const uint32_t ab = sb + SM_HS + myrow * 96 + kh;
            const int n0 = half ? 7 : 0;
            const int NN = half ? 6 : 7;
            float d[7][4];
#pragma unroll
            for (int j = 0; j < 7; j++)
#pragma unroll
                for (int k = 0; k < 4; k++) d[j][k] = 0.f;

#pragma unroll
            for (int kst = 0; kst < 2; kst++) {
                uint32_t ah[4], al[4];
                ldm_x4(ah, ab + kst * 32);
                ldm_x4(al, ab + HS_LO + kst * 32);
                uint4 wv[7];
                for (int j = 0; j < NN; j++)
                    wv[j] = *reinterpret_cast<const uint4*>(buf + (((kst * 13 + n0 + j) * 32 + T) << 4));
                for (int j = 0; j < NN; j++) mma_bf16(d[j], ah, wv[j].x, wv[j].y);
                for (int j = 0; j < NN; j++) mma_bf16(d[j], ah, wv[j].z, wv[j].w);
                for (int j = 0; j < NN; j++) mma_bf16(d[j], al, wv[j].x, wv[j].y);
            }
            {   // k8 tail (h 32..39)
                uint32_t ah[2], al[2];
                ldm_x2(ah, sb + SM_HS + myrow * 96 + 64);
                ldm_x2(al, sb + SM_HS + HS_LO + myrow * 96 + 64);
                for (int j = 0; j < NN; j++) {
                    const uint4 wv = *reinterpret_cast<const uint4*>(buf + (((26 + n0 + j) * 32 + T) << 4));
                    mma_bf16_k8(d[j], ah[0], ah[1], wv.x);
                    mma_bf16_k8(d[j], ah[0], ah[1], wv.z);
                    mma_bf16_k8(d[j], al[0], al[1], wv.x);
                }
            }
            const int ra = rl[T >> 2], rb = rl[(T >> 2) + 8];
            for (int j = 0; j < NN; j++) {
                const int col = (n0 + j) * 8 + q * 2;
                atomicAdd(&oS[ra * 104 + col],     d[j][0]);
                atomicAdd(&oS[ra * 104 + col + 1], d[j][1]);
                atomicAdd(&oS[rb * 104 + col],     d[j][2]);
                atomicAdd(&oS[rb * 104 + col + 1], d[j][3]);
            }
        }
        __syncthreads();
        if (lead && s + 2 < NSLOT) {
            const int ncs = (40 - 3 * (s + 2) < 3) ? (40 - 3 * (s + 2)) : 3;
            const uint32_t mb = (s & 1) ? mb1 : mb0;
            mbar_expect(mb, (uint32_t)(ncs * IMGB_C));
            bulk_cp(sb + SM_RING + (s & 1) * SLOTSZ, imgB + (size_t)(3 * (s + 2)) * IMGB_C,
                    (uint32_t)(ncs * IMGB_C), mb);
        }
    }

    // ================= epilogue =================
    for (int idx = tid; idx < 128 * 50; idx += NTHR) {
        const int r = idx / 50, f = (idx % 50) * 2;
        float2 a = *reinterpret_cast<const float2*>(&oS[r * 104 + f]);
        float2 bf = *reinterpret_cast<const float2*>(&biasS[f]);
        float2 o;
        o.x = fmaxf(a.x + bf.x, 0.f);
        o.y = fmaxf(a.y + bf.y, 0.f);
        *reinterpret_cast<float2*>(&out[((size_t)(b0 + r) * N_INST + i) * N_FEAT + f]) = o;
    }
}

// ---------------------------------------------------------------------------
extern "C" void kernel_launch(void* const* d_in, const int* in_sizes, int n_in,
                              void* d_out, int out_size) {
    (void)in_sizes; (void)n_in; (void)out_size;
    const float* x    = (const float*)d_in[0];
    const float* mask = (const float*)d_in[1];
    const float* A    = (const float*)d_in[2];
    const float* Bp   = (const float*)d_in[3];
    const float* bfin = (const float*)d_in[4];
    float* out = (float*)d_out;

    cudaFuncSetAttribute(tmsspd_main_kernel,
                         cudaFuncAttributeMaxDynamicSharedMemorySize, SM_TOTAL);

    compute_G_kernel<<<N_INST * NC, 256>>>(A, Bp);

    dim3 grid(B_SZ / 128, N_INST);
    tmsspd_main_kernel<<<grid, NTHR, SM_TOTAL>>>(x, mask, bfin, out);
}